// round 4
// baseline (speedup 1.0000x reference)
#include <cuda_runtime.h>
#include <cuda_bf16.h>
#include <math.h>
#include <stdint.h>

// ===========================================================================
// CBTree B=4, L=9, d=256.
// h_par = tanh(G @ B^T + v),  G=[gl|gr] (M x 512),  B=[Wl|Wr] (256 x 512).
// bf16 hi/lo 3-pass HMMA (mma.sync m16n8k16), fused child-combine in fill.
// CTA: 128(M) x 256(N), 512 thr / 16 warps, warp 32x64, KC=32, 2-stage smem.
// ===========================================================================

#define MTILE 128
#define NDIM  256
#define KC    32
#define NCHUNKS 16            // 512 / 32

#define ST_A_HI 0
#define ST_A_LO 8192
#define ST_B_HI 16384
#define ST_B_LO 32768
#define STAGE   49152
#define SMEM_REQ (2 * STAGE)

// swizzled byte offset of 16B block (row, cblk) in a 64B-row tile
#define SW(r, cb) ((uint32_t)((r) * 64 + (((cb) ^ (((r) >> 1) & 3)) << 4)))

// Scratch (__device__ globals: allocation-free rule)
__device__ float g_h0[16384 * 256];
__device__ float g_h1[16384 * 256];
__device__ uint4 g_Bhi[256 * 512 / 8];   // bf16 [256][512] hi part of [Wl|Wr]
__device__ uint4 g_Blo[256 * 512 / 8];   // bf16 [256][512] lo part

// ---------------------------------------------------------------------------
__device__ __forceinline__ uint32_t smem_u32(const void* p) {
    uint32_t a;
    asm("{ .reg .u64 t; cvta.to.shared.u64 t, %1; cvt.u32.u64 %0, t; }"
        : "=r"(a) : "l"(p));
    return a;
}
__device__ __forceinline__ void ldsm_x4(uint32_t* r, uint32_t addr) {
    asm volatile("ldmatrix.sync.aligned.m8n8.x4.shared.b16 {%0,%1,%2,%3}, [%4];"
                 : "=r"(r[0]), "=r"(r[1]), "=r"(r[2]), "=r"(r[3]) : "r"(addr));
}
__device__ __forceinline__ void mma16816(float* d, const uint32_t* a,
                                         const uint32_t* b) {
    asm volatile(
        "mma.sync.aligned.m16n8k16.row.col.f32.bf16.bf16.f32 "
        "{%0,%1,%2,%3}, {%4,%5,%6,%7}, {%8,%9}, {%0,%1,%2,%3};"
        : "+f"(d[0]), "+f"(d[1]), "+f"(d[2]), "+f"(d[3])
        : "r"(a[0]), "r"(a[1]), "r"(a[2]), "r"(a[3]), "r"(b[0]), "r"(b[1]));
}
__device__ __forceinline__ void split2(float x, float y, uint32_t& hi, uint32_t& lo) {
    __nv_bfloat16 hx = __float2bfloat16(x);
    __nv_bfloat16 hy = __float2bfloat16(y);
    float rx = x - __bfloat162float(hx);
    float ry = y - __bfloat162float(hy);
    hi = (uint32_t)__bfloat16_as_ushort(hx) |
         ((uint32_t)__bfloat16_as_ushort(hy) << 16);
    lo = (uint32_t)__bfloat16_as_ushort(__float2bfloat16(rx)) |
         ((uint32_t)__bfloat16_as_ushort(__float2bfloat16(ry)) << 16);
}

// ---------------------------------------------------------------------------
// B[n][k] = Wl[n][k] (k<256) else Wr[n][k-256]; split to hi/lo bf16.
// ---------------------------------------------------------------------------
__global__ void prep_b(const float* __restrict__ Wl, const float* __restrict__ Wr) {
    int idx = blockIdx.x * 256 + threadIdx.x;   // grid 512 -> 131072
    int n = idx >> 9, k = idx & 511;
    float w = (k < 256) ? Wl[n * 256 + k] : Wr[n * 256 + (k - 256)];
    __nv_bfloat16 h = __float2bfloat16(w);
    float r = w - __bfloat162float(h);
    ((unsigned short*)g_Bhi)[idx] = __bfloat16_as_ushort(h);
    ((unsigned short*)g_Blo)[idx] = __bfloat16_as_ushort(__float2bfloat16(r));
}

// ---------------------------------------------------------------------------
// Fill one K-chunk stage: B copy (swizzled) + fused child-combine A (hi/lo).
// gl = c0 + (2/3)c1 + (1/3)c2 ;  gr = (1/3)c1 + (2/3)c2 + c3
// ---------------------------------------------------------------------------
__device__ __forceinline__ void fill_chunk(char* st, int c,
                                           const float* __restrict__ childs,
                                           int p0, int n_par, int tid) {
    // ---- B: 256 rows x 4 cblk -> 1024 16B-chunks, 2 per thread ----
#pragma unroll
    for (int it = 0; it < 2; it++) {
        int idx  = it * 512 + tid;
        int row  = idx >> 2, cblk = idx & 3;
        int gi   = row * 64 + c * 4 + cblk;
        uint4 vh = g_Bhi[gi];
        uint4 vl = g_Blo[gi];
        uint32_t sw = SW(row, cblk);
        *(uint4*)(st + ST_B_HI + sw) = vh;
        *(uint4*)(st + ST_B_LO + sw) = vl;
    }
    // ---- A: 128 rows x 4 cblk -> 512 chunks, 1 per thread ----
    {
        int row = tid >> 2, cblk = tid & 3;
        int p = p0 + row;
        uint4 uh = make_uint4(0u, 0u, 0u, 0u);
        uint4 ul = make_uint4(0u, 0u, 0u, 0u);
        const bool left = (c < 8);
        if (p < n_par) {
            const int j0 = (left ? c * 32 : (c - 8) * 32) + cblk * 8;
            const float w0 = left ? 1.0f : (1.0f / 3.0f);
            const float w1 = 2.0f / 3.0f;
            const float w2 = left ? (1.0f / 3.0f) : 1.0f;
            const int o0 = left ? 0 : 256;
            const int o1 = left ? 256 : 512;
            const int o2 = left ? 512 : 768;
            const float* cb = childs + (size_t)p * 1024 + j0;
            float4 a0 = *(const float4*)(cb + o0);
            float4 a1 = *(const float4*)(cb + o0 + 4);
            float4 b0 = *(const float4*)(cb + o1);
            float4 b1 = *(const float4*)(cb + o1 + 4);
            float4 d0 = *(const float4*)(cb + o2);
            float4 d1 = *(const float4*)(cb + o2 + 4);
            float g0 = w0 * a0.x + w1 * b0.x + w2 * d0.x;
            float g1 = w0 * a0.y + w1 * b0.y + w2 * d0.y;
            float g2 = w0 * a0.z + w1 * b0.z + w2 * d0.z;
            float g3 = w0 * a0.w + w1 * b0.w + w2 * d0.w;
            float g4 = w0 * a1.x + w1 * b1.x + w2 * d1.x;
            float g5 = w0 * a1.y + w1 * b1.y + w2 * d1.y;
            float g6 = w0 * a1.z + w1 * b1.z + w2 * d1.z;
            float g7 = w0 * a1.w + w1 * b1.w + w2 * d1.w;
            split2(g0, g1, uh.x, ul.x);
            split2(g2, g3, uh.y, ul.y);
            split2(g4, g5, uh.z, ul.z);
            split2(g6, g7, uh.w, ul.w);
        }
        uint32_t sw = SW(row, cblk);
        *(uint4*)(st + ST_A_HI + sw) = uh;
        *(uint4*)(st + ST_A_LO + sw) = ul;
    }
}

// ---------------------------------------------------------------------------
__global__ void __launch_bounds__(512, 1) level_mma(
    const float* __restrict__ childs,
    const float* __restrict__ vecs,
    float* __restrict__ out,
    int n_par)
{
    extern __shared__ char smem[];
    const uint32_t sbase = smem_u32(smem);
    const int tid  = threadIdx.x;
    const int warp = tid >> 5;
    const int lane = tid & 31;
    const int wm   = warp & 3;          // M block: wm*32
    const int wn   = warp >> 2;         // N block: wn*64
    const int p0   = blockIdx.x * MTILE;

    float acc[2][8][4];
#pragma unroll
    for (int i = 0; i < 2; i++)
#pragma unroll
        for (int j = 0; j < 8; j++)
#pragma unroll
            for (int q = 0; q < 4; q++) acc[i][j][q] = 0.0f;

    fill_chunk(smem, 0, childs, p0, n_par, tid);
    __syncthreads();

    for (int c = 0; c < NCHUNKS; c++) {
        const int s = c & 1;
        if (c + 1 < NCHUNKS)
            fill_chunk(smem + (s ^ 1) * STAGE, c + 1, childs, p0, n_par, tid);

        const uint32_t sA = sbase + s * STAGE;
        const uint32_t sB = sA + ST_B_HI;
#pragma unroll
        for (int ks = 0; ks < 2; ks++) {
            uint32_t ah[2][4], al[2][4];
            const int arow = wm * 32 + (lane & 15);
            const int acb  = ks * 2 + (lane >> 4);
#pragma unroll
            for (int mi = 0; mi < 2; mi++) {
                uint32_t ad = sA + SW(arow + mi * 16, acb);
                ldsm_x4(ah[mi], ad);
                ldsm_x4(al[mi], ad + ST_A_LO);
            }
#pragma unroll
            for (int nq = 0; nq < 4; nq++) {
                const int brow = wn * 64 + nq * 16 + (lane & 15);
                uint32_t bd = sB + SW(brow, ks * 2 + (lane >> 4));
                uint32_t qh[4], ql[4];
                ldsm_x4(qh, bd);
                ldsm_x4(ql, bd + 16384);           // ST_B_LO - ST_B_HI
                uint32_t bh0[2] = {qh[0], qh[2]}, bh1[2] = {qh[1], qh[3]};
                uint32_t bl0[2] = {ql[0], ql[2]}, bl1[2] = {ql[1], ql[3]};
#pragma unroll
                for (int mi = 0; mi < 2; mi++) {
                    mma16816(acc[mi][nq * 2],     ah[mi], bh0);
                    mma16816(acc[mi][nq * 2],     al[mi], bh0);
                    mma16816(acc[mi][nq * 2],     ah[mi], bl0);
                    mma16816(acc[mi][nq * 2 + 1], ah[mi], bh1);
                    mma16816(acc[mi][nq * 2 + 1], al[mi], bh1);
                    mma16816(acc[mi][nq * 2 + 1], ah[mi], bl1);
                }
            }
        }
        __syncthreads();
    }

    // ---- epilogue: + vec, tanh, store fp32 ----
#pragma unroll
    for (int mi = 0; mi < 2; mi++) {
        const int r0 = p0 + wm * 32 + mi * 16 + (lane >> 2);
        const int r1 = r0 + 8;
#pragma unroll
        for (int ni = 0; ni < 8; ni++) {
            const int col = wn * 64 + ni * 8 + (lane & 3) * 2;
            if (r0 < n_par) {
                const float* vp = vecs + (size_t)r0 * 256 + col;
                float* op = out + (size_t)r0 * 256 + col;
                float2 v = *(const float2*)vp;
                float2 rr;
                rr.x = tanhf(acc[mi][ni][0] + v.x);
                rr.y = tanhf(acc[mi][ni][1] + v.y);
                *(float2*)op = rr;
            }
            if (r1 < n_par) {
                const float* vp = vecs + (size_t)r1 * 256 + col;
                float* op = out + (size_t)r1 * 256 + col;
                float2 v = *(const float2*)vp;
                float2 rr;
                rr.x = tanhf(acc[mi][ni][2] + v.x);
                rr.y = tanhf(acc[mi][ni][3] + v.y);
                *(float2*)op = rr;
            }
        }
    }
}

// ---------------------------------------------------------------------------
extern "C" void kernel_launch(void* const* d_in, const int* in_sizes, int n_in,
                              void* d_out, int out_size) {
    const float* vectors = (const float*)d_in[0];
    const float* Wl = (const float*)d_in[1];
    const float* Wr = (const float*)d_in[2];

    static float* h0 = nullptr;
    static float* h1 = nullptr;
    static bool inited = false;
    if (!inited) {
        cudaGetSymbolAddress((void**)&h0, g_h0);
        cudaGetSymbolAddress((void**)&h1, g_h1);
        cudaFuncSetAttribute(level_mma,
                             cudaFuncAttributeMaxDynamicSharedMemorySize, SMEM_REQ);
        inited = true;
    }

    prep_b<<<512, 256>>>(Wl, Wr);

    const float* cur = vectors + (size_t)21845 * 256;   // leaves (level 8)
    for (int l = 7; l >= 0; l--) {
        int n_par = 1 << (2 * l);
        size_t off = (size_t)(((1u << (2 * l)) - 1u) / 3u);
        const float* vecs = vectors + off * 256;
        float* out = (l == 0) ? (float*)d_out : ((l & 1) ? h0 : h1);
        int grid = (n_par + MTILE - 1) / MTILE;
        level_mma<<<grid, 512, SMEM_REQ>>>(cur, vecs, out, n_par);
        cur = out;
    }
}

// round 5
// speedup vs baseline: 2.5546x; 2.5546x over previous
#include <cuda_runtime.h>
#include <cuda_bf16.h>
#include <math.h>
#include <stdint.h>

// ===========================================================================
// CBTree B=4, L=9, d=256.
// h_par = tanh(G @ B^T + v),  G=[gl|gr] (M x 512),  B=[Wl|Wr] (256 x 512).
//   gl = c0 + (2/3)c1 + (1/3)c2 ;  gr = (1/3)c1 + (2/3)c2 + c3
// Levels n_par>=256: bf16 hi/lo 3-pass HMMA (mma.sync m16n8k16),
//   CTA = 64(M) x 128(N), 8 warps, 2-stage smem 2x24KB, 2 CTAs/SM.
// Levels n_par<=64: fp32 SIMT, grid n_par*8 (32 cols x 8 K-slices per CTA).
// ===========================================================================

#define MTILE 64
#define NTILE 128
#define NCHUNKS 16            // K=512 / KC=32

#define ST_A_HI 0
#define ST_A_LO 4096
#define ST_B_HI 8192
#define ST_B_LO 16384
#define STAGE   24576
#define SMEM_REQ (2 * STAGE)  // 48 KB

// swizzled byte offset of 16B block (row, cblk) in a 64B-row tile
#define SW(r, cb) ((uint32_t)((r) * 64 + (((cb) ^ (((r) >> 1) & 3)) << 4)))

// Scratch (__device__ globals: allocation-free rule)
__device__ float g_h0[16384 * 256];
__device__ float g_h1[16384 * 256];
__device__ uint4 g_Bhi[256 * 512 / 8];   // bf16 [256][512] hi part of [Wl|Wr]
__device__ uint4 g_Blo[256 * 512 / 8];   // bf16 [256][512] lo part

// ---------------------------------------------------------------------------
__device__ __forceinline__ uint32_t smem_u32(const void* p) {
    uint32_t a;
    asm("{ .reg .u64 t; cvta.to.shared.u64 t, %1; cvt.u32.u64 %0, t; }"
        : "=r"(a) : "l"(p));
    return a;
}
__device__ __forceinline__ void ldsm_x4(uint32_t* r, uint32_t addr) {
    asm volatile("ldmatrix.sync.aligned.m8n8.x4.shared.b16 {%0,%1,%2,%3}, [%4];"
                 : "=r"(r[0]), "=r"(r[1]), "=r"(r[2]), "=r"(r[3]) : "r"(addr));
}
__device__ __forceinline__ void mma16816(float* d, const uint32_t* a,
                                         const uint32_t* b) {
    asm volatile(
        "mma.sync.aligned.m16n8k16.row.col.f32.bf16.bf16.f32 "
        "{%0,%1,%2,%3}, {%4,%5,%6,%7}, {%8,%9}, {%0,%1,%2,%3};"
        : "+f"(d[0]), "+f"(d[1]), "+f"(d[2]), "+f"(d[3])
        : "r"(a[0]), "r"(a[1]), "r"(a[2]), "r"(a[3]), "r"(b[0]), "r"(b[1]));
}
__device__ __forceinline__ void split2(float x, float y, uint32_t& hi, uint32_t& lo) {
    __nv_bfloat16 hx = __float2bfloat16(x);
    __nv_bfloat16 hy = __float2bfloat16(y);
    float rx = x - __bfloat162float(hx);
    float ry = y - __bfloat162float(hy);
    hi = (uint32_t)__bfloat16_as_ushort(hx) |
         ((uint32_t)__bfloat16_as_ushort(hy) << 16);
    lo = (uint32_t)__bfloat16_as_ushort(__float2bfloat16(rx)) |
         ((uint32_t)__bfloat16_as_ushort(__float2bfloat16(ry)) << 16);
}

// ---------------------------------------------------------------------------
// B[n][k] = Wl[n][k] (k<256) else Wr[n][k-256]; split to hi/lo bf16.
// ---------------------------------------------------------------------------
__global__ void prep_b(const float* __restrict__ Wl, const float* __restrict__ Wr) {
    int idx = blockIdx.x * 256 + threadIdx.x;   // grid 512 -> 131072
    int n = idx >> 9, k = idx & 511;
    float w = (k < 256) ? Wl[n * 256 + k] : Wr[n * 256 + (k - 256)];
    __nv_bfloat16 h = __float2bfloat16(w);
    float r = w - __bfloat162float(h);
    ((unsigned short*)g_Bhi)[idx] = __bfloat16_as_ushort(h);
    ((unsigned short*)g_Blo)[idx] = __bfloat16_as_ushort(__float2bfloat16(r));
}

// ---------------------------------------------------------------------------
// Fill one K-chunk stage: B copy (swizzled) + fused child-combine A (hi/lo).
// ---------------------------------------------------------------------------
__device__ __forceinline__ void fill_chunk(char* st, int c,
                                           const float* __restrict__ childs,
                                           int p0, int n0, int tid) {
    // ---- B: 128 rows x 4 cblk -> 512 16B-chunks, 2 per thread ----
#pragma unroll
    for (int it = 0; it < 2; it++) {
        int idx  = it * 256 + tid;
        int row  = idx >> 2, cblk = idx & 3;
        int gi   = (n0 + row) * 64 + c * 4 + cblk;
        uint4 vh = g_Bhi[gi];
        uint4 vl = g_Blo[gi];
        uint32_t sw = SW(row, cblk);
        *(uint4*)(st + ST_B_HI + sw) = vh;
        *(uint4*)(st + ST_B_LO + sw) = vl;
    }
    // ---- A: 64 rows x 4 cblk -> 256 chunks, 1 per thread ----
    {
        int row = tid >> 2, cblk = tid & 3;
        int p = p0 + row;
        const bool left = (c < 8);
        const int j0 = (left ? c * 32 : (c - 8) * 32) + cblk * 8;
        const float w0 = left ? 1.0f : (1.0f / 3.0f);
        const float w1 = 2.0f / 3.0f;
        const float w2 = left ? (1.0f / 3.0f) : 1.0f;
        const int o0 = left ? 0 : 256;
        const int o1 = left ? 256 : 512;
        const int o2 = left ? 512 : 768;
        const float* cb = childs + (size_t)p * 1024 + j0;
        float4 a0 = *(const float4*)(cb + o0);
        float4 a1 = *(const float4*)(cb + o0 + 4);
        float4 b0 = *(const float4*)(cb + o1);
        float4 b1 = *(const float4*)(cb + o1 + 4);
        float4 d0 = *(const float4*)(cb + o2);
        float4 d1 = *(const float4*)(cb + o2 + 4);
        float g0 = w0 * a0.x + w1 * b0.x + w2 * d0.x;
        float g1 = w0 * a0.y + w1 * b0.y + w2 * d0.y;
        float g2 = w0 * a0.z + w1 * b0.z + w2 * d0.z;
        float g3 = w0 * a0.w + w1 * b0.w + w2 * d0.w;
        float g4 = w0 * a1.x + w1 * b1.x + w2 * d1.x;
        float g5 = w0 * a1.y + w1 * b1.y + w2 * d1.y;
        float g6 = w0 * a1.z + w1 * b1.z + w2 * d1.z;
        float g7 = w0 * a1.w + w1 * b1.w + w2 * d1.w;
        uint4 uh, ul;
        split2(g0, g1, uh.x, ul.x);
        split2(g2, g3, uh.y, ul.y);
        split2(g4, g5, uh.z, ul.z);
        split2(g6, g7, uh.w, ul.w);
        uint32_t sw = SW(row, cblk);
        *(uint4*)(st + ST_A_HI + sw) = uh;
        *(uint4*)(st + ST_A_LO + sw) = ul;
    }
}

// ---------------------------------------------------------------------------
// HMMA level kernel: grid (n_par/64, 2), 256 thr / 8 warps.
// Warp tile 32(M) x 32(N): wm = warp&1, wn = warp>>1.
// Requires n_par % 64 == 0 (true for n_par >= 256 levels).
// ---------------------------------------------------------------------------
__global__ void __launch_bounds__(256, 2) level_mma(
    const float* __restrict__ childs,
    const float* __restrict__ vecs,
    float* __restrict__ out,
    int n_par)
{
    extern __shared__ char smem[];
    const uint32_t sbase = smem_u32(smem);
    const int tid  = threadIdx.x;
    const int warp = tid >> 5;
    const int lane = tid & 31;
    const int wm   = warp & 1;          // M 32-block
    const int wn   = warp >> 1;         // N 32-block (0..3)
    const int p0   = blockIdx.x * MTILE;
    const int n0   = blockIdx.y * NTILE;

    float acc[2][4][4];
#pragma unroll
    for (int i = 0; i < 2; i++)
#pragma unroll
        for (int j = 0; j < 4; j++)
#pragma unroll
            for (int q = 0; q < 4; q++) acc[i][j][q] = 0.0f;

    fill_chunk(smem, 0, childs, p0, n0, tid);
    __syncthreads();

    for (int c = 0; c < NCHUNKS; c++) {
        const int s = c & 1;
        if (c + 1 < NCHUNKS)
            fill_chunk(smem + (s ^ 1) * STAGE, c + 1, childs, p0, n0, tid);

        const uint32_t sA = sbase + s * STAGE;
#pragma unroll
        for (int ks = 0; ks < 2; ks++) {
            const int acb = ks * 2 + (lane >> 4);
            uint32_t ah[2][4], al[2][4];
            const int arow = wm * 32 + (lane & 15);
#pragma unroll
            for (int mi = 0; mi < 2; mi++) {
                uint32_t ad = sA + ST_A_HI + SW(arow + mi * 16, acb);
                ldsm_x4(ah[mi], ad);
                ldsm_x4(al[mi], ad + (ST_A_LO - ST_A_HI));
            }
#pragma unroll
            for (int nq = 0; nq < 2; nq++) {
                const int brow = wn * 32 + nq * 16 + (lane & 15);
                uint32_t bd = sA + ST_B_HI + SW(brow, acb);
                uint32_t qh[4], ql[4];
                ldsm_x4(qh, bd);
                ldsm_x4(ql, bd + (ST_B_LO - ST_B_HI));
                uint32_t bh0[2] = {qh[0], qh[2]}, bh1[2] = {qh[1], qh[3]};
                uint32_t bl0[2] = {ql[0], ql[2]}, bl1[2] = {ql[1], ql[3]};
#pragma unroll
                for (int mi = 0; mi < 2; mi++) {
                    mma16816(acc[mi][nq * 2],     ah[mi], bh0);
                    mma16816(acc[mi][nq * 2],     al[mi], bh0);
                    mma16816(acc[mi][nq * 2],     ah[mi], bl0);
                    mma16816(acc[mi][nq * 2 + 1], ah[mi], bh1);
                    mma16816(acc[mi][nq * 2 + 1], al[mi], bh1);
                    mma16816(acc[mi][nq * 2 + 1], ah[mi], bl1);
                }
            }
        }
        __syncthreads();
    }

    // ---- epilogue: + vec, tanh, store fp32 ----
#pragma unroll
    for (int mi = 0; mi < 2; mi++) {
        const int r0 = p0 + wm * 32 + mi * 16 + (lane >> 2);
        const int r1 = r0 + 8;
#pragma unroll
        for (int nj = 0; nj < 4; nj++) {
            const int col = n0 + wn * 32 + nj * 8 + (lane & 3) * 2;
            {
                const float* vp = vecs + (size_t)r0 * 256 + col;
                float* op = out + (size_t)r0 * 256 + col;
                float2 v = *(const float2*)vp;
                float2 rr;
                rr.x = tanhf(acc[mi][nj][0] + v.x);
                rr.y = tanhf(acc[mi][nj][1] + v.y);
                *(float2*)op = rr;
            }
            {
                const float* vp = vecs + (size_t)r1 * 256 + col;
                float* op = out + (size_t)r1 * 256 + col;
                float2 v = *(const float2*)vp;
                float2 rr;
                rr.x = tanhf(acc[mi][nj][2] + v.x);
                rr.y = tanhf(acc[mi][nj][3] + v.y);
                *(float2*)op = rr;
            }
        }
    }
}

// ---------------------------------------------------------------------------
// Small-level fp32 kernel: grid = n_par*8, 256 thr = 32 cols x 8 K-slices.
// CTA (p, cg) computes cols [cg*32, cg*32+32) of parent p.
// ---------------------------------------------------------------------------
__global__ void __launch_bounds__(256) level_small(
    const float* __restrict__ childs,
    const float* __restrict__ Wl,
    const float* __restrict__ Wr,
    const float* __restrict__ vecs,
    float* __restrict__ out)
{
    __shared__ float G[512];
    __shared__ float part[8][33];
    const int tid = threadIdx.x;
    const int p   = blockIdx.x >> 3;
    const int cg  = blockIdx.x & 7;
    const float c23 = 2.0f / 3.0f, c13 = 1.0f / 3.0f;

    {   // build G (each thread 2 entries)
        const float* cb = childs + (size_t)p * 1024;
        int j = tid;                      // 0..255 -> gl
        G[j] = cb[j] + c23 * cb[256 + j] + c13 * cb[512 + j];
        G[256 + j] = c13 * cb[256 + j] + c23 * cb[512 + j] + cb[768 + j];
    }
    __syncthreads();

    const int cc = tid & 31;              // col within group
    const int kg = tid >> 5;              // K slice 0..7 (64 each)
    const int n  = cg * 32 + cc;
    const float* src = (kg < 4) ? (Wl + (size_t)n * 256 + kg * 64)
                                : (Wr + (size_t)n * 256 + (kg - 4) * 64);
    const float* g = G + kg * 64;

    float a0 = 0.f, a1 = 0.f, a2 = 0.f, a3 = 0.f;
#pragma unroll
    for (int i = 0; i < 64; i += 4) {
        float4 w = *(const float4*)(src + i);
        float4 gg = *(const float4*)(g + i);
        a0 = fmaf(gg.x, w.x, a0);
        a1 = fmaf(gg.y, w.y, a1);
        a2 = fmaf(gg.z, w.z, a2);
        a3 = fmaf(gg.w, w.w, a3);
    }
    part[kg][cc] = (a0 + a1) + (a2 + a3);
    __syncthreads();

    if (tid < 32) {
        float s = 0.f;
#pragma unroll
        for (int k = 0; k < 8; k++) s += part[k][tid];
        const int col = cg * 32 + tid;
        out[(size_t)p * 256 + col] = tanhf(s + vecs[(size_t)p * 256 + col]);
    }
}

// ---------------------------------------------------------------------------
extern "C" void kernel_launch(void* const* d_in, const int* in_sizes, int n_in,
                              void* d_out, int out_size) {
    const float* vectors = (const float*)d_in[0];
    const float* Wl = (const float*)d_in[1];
    const float* Wr = (const float*)d_in[2];

    static float* h0 = nullptr;
    static float* h1 = nullptr;
    static bool inited = false;
    if (!inited) {
        cudaGetSymbolAddress((void**)&h0, g_h0);
        cudaGetSymbolAddress((void**)&h1, g_h1);
        cudaFuncSetAttribute(level_mma,
                             cudaFuncAttributeMaxDynamicSharedMemorySize, SMEM_REQ);
        inited = true;
    }

    prep_b<<<512, 256>>>(Wl, Wr);

    const float* cur = vectors + (size_t)21845 * 256;   // leaves (level 8)
    for (int l = 7; l >= 0; l--) {
        int n_par = 1 << (2 * l);
        size_t off = (size_t)(((1u << (2 * l)) - 1u) / 3u);
        const float* vecs = vectors + off * 256;
        float* out = (l == 0) ? (float*)d_out : ((l & 1) ? h0 : h1);
        if (n_par >= 256) {
            level_mma<<<dim3(n_par / MTILE, 2), 256, SMEM_REQ>>>(cur, vecs, out, n_par);
        } else {
            level_small<<<n_par * 8, 256>>>(cur, Wl, Wr, vecs, out);
        }
        cur = out;
    }
}

// round 8
// speedup vs baseline: 2.9676x; 1.1617x over previous
#include <cuda_runtime.h>
#include <cuda_bf16.h>
#include <math.h>
#include <stdint.h>

// ===========================================================================
// CBTree B=4, L=9, d=256.
// h_par = tanh(G @ B^T + v),  G=[gl|gr] (M x 512),  B=[Wl|Wr] (256 x 512).
//   gl = c0 + (2/3)c1 + (1/3)c2 ;  gr = (1/3)c1 + (2/3)c2 + c3
// n_par>=1024: bf16 hi/lo 3-pass HMMA, CTA 64x128, cp.async-pipelined fill,
//   K-split across blockIdx.z for mid levels (+ reduce/tanh kernel).
// n_par<=256: fp32 SIMT, grid n_par*8.
// ===========================================================================

#define MTILE 64
#define NTILE 128

#define ST_A_HI 0
#define ST_A_LO 4096
#define ST_B_HI 8192
#define ST_B_LO 16384
#define STAGE   24576
#define SMEM_REQ (2 * STAGE)  // 48 KB

// swizzled byte offset of 16B block (row, cblk) in a 64B-row tile
#define SW(r, cb) ((uint32_t)((r) * 64 + (((cb) ^ (((r) >> 1) & 3)) << 4)))

// Scratch (__device__ globals: allocation-free rule)
__device__ float g_h0[16384 * 256];      // 16 MB ping
__device__ float g_h1[16384 * 256];      // 16 MB pong
__device__ float g_part[2097152];        // 8 MB K-split partials
__device__ uint4 g_Bhi[256 * 512 / 8];   // bf16 [256][512] hi of [Wl|Wr]
__device__ uint4 g_Blo[256 * 512 / 8];   // bf16 [256][512] lo

// ---------------------------------------------------------------------------
__device__ __forceinline__ uint32_t smem_u32(const void* p) {
    uint32_t a;
    asm("{ .reg .u64 t; cvta.to.shared.u64 t, %1; cvt.u32.u64 %0, t; }"
        : "=r"(a) : "l"(p));
    return a;
}
__device__ __forceinline__ void ldsm_x4(uint32_t* r, uint32_t addr) {
    asm volatile("ldmatrix.sync.aligned.m8n8.x4.shared.b16 {%0,%1,%2,%3}, [%4];"
                 : "=r"(r[0]), "=r"(r[1]), "=r"(r[2]), "=r"(r[3]) : "r"(addr));
}
__device__ __forceinline__ void mma16816(float* d, const uint32_t* a,
                                         const uint32_t* b) {
    asm volatile(
        "mma.sync.aligned.m16n8k16.row.col.f32.bf16.bf16.f32 "
        "{%0,%1,%2,%3}, {%4,%5,%6,%7}, {%8,%9}, {%0,%1,%2,%3};"
        : "+f"(d[0]), "+f"(d[1]), "+f"(d[2]), "+f"(d[3])
        : "r"(a[0]), "r"(a[1]), "r"(a[2]), "r"(a[3]), "r"(b[0]), "r"(b[1]));
}
__device__ __forceinline__ void cp_async16(uint32_t dst, const void* src) {
    asm volatile("cp.async.cg.shared.global [%0], [%1], 16;"
                 :: "r"(dst), "l"(src) : "memory");
}
#define CP_COMMIT() asm volatile("cp.async.commit_group;" ::: "memory")
#define CP_WAIT0()  asm volatile("cp.async.wait_group 0;" ::: "memory")

__device__ __forceinline__ void split2(float x, float y, uint32_t& hi, uint32_t& lo) {
    __nv_bfloat16 hx = __float2bfloat16(x);
    __nv_bfloat16 hy = __float2bfloat16(y);
    float rx = x - __bfloat162float(hx);
    float ry = y - __bfloat162float(hy);
    hi = (uint32_t)__bfloat16_as_ushort(hx) |
         ((uint32_t)__bfloat16_as_ushort(hy) << 16);
    lo = (uint32_t)__bfloat16_as_ushort(__float2bfloat16(rx)) |
         ((uint32_t)__bfloat16_as_ushort(__float2bfloat16(ry)) << 16);
}

// ---------------------------------------------------------------------------
__global__ void prep_b(const float* __restrict__ Wl, const float* __restrict__ Wr) {
    int idx = blockIdx.x * 256 + threadIdx.x;   // grid 512 -> 131072
    int n = idx >> 9, k = idx & 511;
    float w = (k < 256) ? Wl[n * 256 + k] : Wr[n * 256 + (k - 256)];
    __nv_bfloat16 h = __float2bfloat16(w);
    float r = w - __bfloat162float(h);
    ((unsigned short*)g_Bhi)[idx] = __bfloat16_as_ushort(h);
    ((unsigned short*)g_Blo)[idx] = __bfloat16_as_ushort(__float2bfloat16(r));
}

// ---------------------------------------------------------------------------
// A path: load children (6 float4 regs), then combine+split+STS.
// ---------------------------------------------------------------------------
struct ARegs { float4 a0, a1, b0, b1, d0, d1; };

__device__ __forceinline__ void load_A(int c, const float* __restrict__ childs,
                                       int p0, int tid, ARegs& ar) {
    const bool left = (c < 8);
    const int row = tid >> 2, cblk = tid & 3;
    const int j0 = (left ? c * 32 : (c - 8) * 32) + cblk * 8;
    const int o0 = left ? 0 : 256;
    const float* cb = childs + (size_t)(p0 + row) * 1024 + j0;
    ar.a0 = *(const float4*)(cb + o0);
    ar.a1 = *(const float4*)(cb + o0 + 4);
    ar.b0 = *(const float4*)(cb + o0 + 256);
    ar.b1 = *(const float4*)(cb + o0 + 260);
    ar.d0 = *(const float4*)(cb + o0 + 512);
    ar.d1 = *(const float4*)(cb + o0 + 516);
}

__device__ __forceinline__ void store_A(int c, const ARegs& ar, char* st, int tid) {
    const bool left = (c < 8);
    const float w0 = left ? 1.0f : (1.0f / 3.0f);
    const float w1 = 2.0f / 3.0f;
    const float w2 = left ? (1.0f / 3.0f) : 1.0f;
    float g0 = w0 * ar.a0.x + w1 * ar.b0.x + w2 * ar.d0.x;
    float g1 = w0 * ar.a0.y + w1 * ar.b0.y + w2 * ar.d0.y;
    float g2 = w0 * ar.a0.z + w1 * ar.b0.z + w2 * ar.d0.z;
    float g3 = w0 * ar.a0.w + w1 * ar.b0.w + w2 * ar.d0.w;
    float g4 = w0 * ar.a1.x + w1 * ar.b1.x + w2 * ar.d1.x;
    float g5 = w0 * ar.a1.y + w1 * ar.b1.y + w2 * ar.d1.y;
    float g6 = w0 * ar.a1.z + w1 * ar.b1.z + w2 * ar.d1.z;
    float g7 = w0 * ar.a1.w + w1 * ar.b1.w + w2 * ar.d1.w;
    uint4 uh, ul;
    split2(g0, g1, uh.x, ul.x);
    split2(g2, g3, uh.y, ul.y);
    split2(g4, g5, uh.z, ul.z);
    split2(g6, g7, uh.w, ul.w);
    const int row = tid >> 2, cblk = tid & 3;
    uint32_t sw = SW(row, cblk);
    *(uint4*)(st + ST_A_HI + sw) = uh;
    *(uint4*)(st + ST_A_LO + sw) = ul;
}

// B: 128 rows x 4 cblk x {hi,lo} -> 4 cp.async of 16B per thread
__device__ __forceinline__ void fill_B_async(uint32_t stage, int c, int n0, int tid) {
#pragma unroll
    for (int it = 0; it < 2; it++) {
        int idx  = it * 256 + tid;
        int row  = idx >> 2, cblk = idx & 3;
        int gi   = (n0 + row) * 64 + c * 4 + cblk;
        uint32_t sw = SW(row, cblk);
        cp_async16(stage + ST_B_HI + sw, g_Bhi + gi);
        cp_async16(stage + ST_B_LO + sw, g_Blo + gi);
    }
}

// ---------------------------------------------------------------------------
// HMMA level kernel. grid (n_par/64, 2, ksplit); chunk range [z*nc, z*nc+nc).
// vecs == null -> partial (raw fp32 store to out + z*zstride).
// ---------------------------------------------------------------------------
__global__ void __launch_bounds__(256, 2) level_mma(
    const float* __restrict__ childs,
    const float* __restrict__ vecs,
    float* __restrict__ out,
    int nc, size_t zstride)
{
    extern __shared__ char smem[];
    const uint32_t sbase = smem_u32(smem);
    const int tid  = threadIdx.x;
    const int warp = tid >> 5;
    const int lane = tid & 31;
    const int wm   = warp & 1;
    const int wn   = warp >> 1;
    const int p0   = blockIdx.x * MTILE;
    const int n0   = blockIdx.y * NTILE;
    const int c0   = blockIdx.z * nc;
    float* outz = out + (size_t)blockIdx.z * zstride;

    float acc[2][4][4];
#pragma unroll
    for (int i = 0; i < 2; i++)
#pragma unroll
        for (int j = 0; j < 4; j++)
#pragma unroll
            for (int q = 0; q < 4; q++) acc[i][j][q] = 0.0f;

    ARegs ar;
    // prologue: chunk c0 -> stage 0
    load_A(c0, childs, p0, tid, ar);
    fill_B_async(sbase, c0, n0, tid);
    CP_COMMIT();
    store_A(c0, ar, smem, tid);

    for (int i = 0; i < nc; i++) {
        const int c = c0 + i;
        const int s = i & 1;
        CP_WAIT0();
        __syncthreads();            // stage s ready (B arrived, A stored, readers drained)

        const bool more = (i + 1 < nc);
        if (more) {
            load_A(c + 1, childs, p0, tid, ar);
            fill_B_async(sbase + (s ^ 1) * STAGE, c + 1, n0, tid);
            CP_COMMIT();
        }

        const uint32_t sA = sbase + s * STAGE;
#pragma unroll
        for (int ks = 0; ks < 2; ks++) {
            const int acb = ks * 2 + (lane >> 4);
            uint32_t ah[2][4], al[2][4];
            const int arow = wm * 32 + (lane & 15);
#pragma unroll
            for (int mi = 0; mi < 2; mi++) {
                uint32_t ad = sA + ST_A_HI + SW(arow + mi * 16, acb);
                ldsm_x4(ah[mi], ad);
                ldsm_x4(al[mi], ad + (ST_A_LO - ST_A_HI));
            }
#pragma unroll
            for (int nq = 0; nq < 2; nq++) {
                const int brow = wn * 32 + nq * 16 + (lane & 15);
                uint32_t bd = sA + ST_B_HI + SW(brow, acb);
                uint32_t qh[4], ql[4];
                ldsm_x4(qh, bd);
                ldsm_x4(ql, bd + (ST_B_LO - ST_B_HI));
                uint32_t bh0[2] = {qh[0], qh[2]}, bh1[2] = {qh[1], qh[3]};
                uint32_t bl0[2] = {ql[0], ql[2]}, bl1[2] = {ql[1], ql[3]};
#pragma unroll
                for (int mi = 0; mi < 2; mi++) {
                    mma16816(acc[mi][nq * 2],     ah[mi], bh0);
                    mma16816(acc[mi][nq * 2],     al[mi], bh0);
                    mma16816(acc[mi][nq * 2],     ah[mi], bl0);
                    mma16816(acc[mi][nq * 2 + 1], ah[mi], bh1);
                    mma16816(acc[mi][nq * 2 + 1], al[mi], bh1);
                    mma16816(acc[mi][nq * 2 + 1], ah[mi], bl1);
                }
            }
        }
        if (more) store_A(c + 1, ar, smem + (s ^ 1) * STAGE, tid);
        __syncthreads();            // readers of stage s done before next overwrite
    }

    // ---- epilogue ----
#pragma unroll
    for (int mi = 0; mi < 2; mi++) {
        const int r0 = p0 + wm * 32 + mi * 16 + (lane >> 2);
        const int r1 = r0 + 8;
#pragma unroll
        for (int nj = 0; nj < 4; nj++) {
            const int col = n0 + wn * 32 + nj * 8 + (lane & 3) * 2;
            if (vecs) {
                float2 v0 = *(const float2*)(vecs + (size_t)r0 * 256 + col);
                float2 v1 = *(const float2*)(vecs + (size_t)r1 * 256 + col);
                float2 q0, q1;
                q0.x = tanhf(acc[mi][nj][0] + v0.x);
                q0.y = tanhf(acc[mi][nj][1] + v0.y);
                q1.x = tanhf(acc[mi][nj][2] + v1.x);
                q1.y = tanhf(acc[mi][nj][3] + v1.y);
                *(float2*)(outz + (size_t)r0 * 256 + col) = q0;
                *(float2*)(outz + (size_t)r1 * 256 + col) = q1;
            } else {
                *(float2*)(outz + (size_t)r0 * 256 + col) =
                    make_float2(acc[mi][nj][0], acc[mi][nj][1]);
                *(float2*)(outz + (size_t)r1 * 256 + col) =
                    make_float2(acc[mi][nj][2], acc[mi][nj][3]);
            }
        }
    }
}

// ---------------------------------------------------------------------------
// reduce K-split partials: out = tanh(sum_z part[z] + v). float4 per thread.
// ---------------------------------------------------------------------------
__global__ void __launch_bounds__(256) reduce_tanh(
    const float* __restrict__ part, const float* __restrict__ vecs,
    float* __restrict__ out, int nsplit, size_t zstride)
{
    size_t i = (size_t)blockIdx.x * 256 + threadIdx.x;   // float4 index
    const float4* p = (const float4*)part + i;
    float4 s = *p;
    for (int z = 1; z < nsplit; z++) {
        float4 t = *(const float4*)(part + z * zstride + i * 4);
        s.x += t.x; s.y += t.y; s.z += t.z; s.w += t.w;
    }
    float4 v = ((const float4*)vecs)[i];
    float4 r;
    r.x = tanhf(s.x + v.x);
    r.y = tanhf(s.y + v.y);
    r.z = tanhf(s.z + v.z);
    r.w = tanhf(s.w + v.w);
    ((float4*)out)[i] = r;
}

// ---------------------------------------------------------------------------
// Small-level fp32 kernel: grid = n_par*8, 256 thr = 32 cols x 8 K-slices.
// ---------------------------------------------------------------------------
__global__ void __launch_bounds__(256) level_small(
    const float* __restrict__ childs,
    const float* __restrict__ Wl,
    const float* __restrict__ Wr,
    const float* __restrict__ vecs,
    float* __restrict__ out)
{
    __shared__ float G[512];
    __shared__ float part[8][33];
    const int tid = threadIdx.x;
    const int p   = blockIdx.x >> 3;
    const int cg  = blockIdx.x & 7;
    const float c23 = 2.0f / 3.0f, c13 = 1.0f / 3.0f;

    {
        const float* cb = childs + (size_t)p * 1024;
        int j = tid;
        G[j] = cb[j] + c23 * cb[256 + j] + c13 * cb[512 + j];
        G[256 + j] = c13 * cb[256 + j] + c23 * cb[512 + j] + cb[768 + j];
    }
    __syncthreads();

    const int cc = tid & 31;
    const int kg = tid >> 5;
    const int n  = cg * 32 + cc;
    const float* src = (kg < 4) ? (Wl + (size_t)n * 256 + kg * 64)
                                : (Wr + (size_t)n * 256 + (kg - 4) * 64);
    const float* g = G + kg * 64;

    float a0 = 0.f, a1 = 0.f, a2 = 0.f, a3 = 0.f;
#pragma unroll
    for (int i = 0; i < 64; i += 4) {
        float4 w = *(const float4*)(src + i);
        float4 gg = *(const float4*)(g + i);
        a0 = fmaf(gg.x, w.x, a0);
        a1 = fmaf(gg.y, w.y, a1);
        a2 = fmaf(gg.z, w.z, a2);
        a3 = fmaf(gg.w, w.w, a3);
    }
    part[kg][cc] = (a0 + a1) + (a2 + a3);
    __syncthreads();

    if (tid < 32) {
        float s = 0.f;
#pragma unroll
        for (int k = 0; k < 8; k++) s += part[k][tid];
        const int col = cg * 32 + tid;
        out[(size_t)p * 256 + col] = tanhf(s + vecs[(size_t)p * 256 + col]);
    }
}

// ---------------------------------------------------------------------------
extern "C" void kernel_launch(void* const* d_in, const int* in_sizes, int n_in,
                              void* d_out, int out_size) {
    const float* vectors = (const float*)d_in[0];
    const float* Wl = (const float*)d_in[1];
    const float* Wr = (const float*)d_in[2];

    static float* h0 = nullptr;
    static float* h1 = nullptr;
    static float* part = nullptr;
    static bool inited = false;
    if (!inited) {
        cudaGetSymbolAddress((void**)&h0, g_h0);
        cudaGetSymbolAddress((void**)&h1, g_h1);
        cudaGetSymbolAddress((void**)&part, g_part);
        cudaFuncSetAttribute(level_mma,
                             cudaFuncAttributeMaxDynamicSharedMemorySize, SMEM_REQ);
        inited = true;
    }

    prep_b<<<512, 256>>>(Wl, Wr);

    const float* cur = vectors + (size_t)21845 * 256;   // leaves (level 8)
    for (int l = 7; l >= 0; l--) {
        int n_par = 1 << (2 * l);
        size_t off = (size_t)(((1u << (2 * l)) - 1u) / 3u);
        const float* vecs = vectors + off * 256;
        float* out = (l == 0) ? (float*)d_out : ((l & 1) ? h0 : h1);
        if (n_par >= 16384) {
            // full K in one CTA, fused epilogue
            level_mma<<<dim3(n_par / MTILE, 2, 1), 256, SMEM_REQ>>>(
                cur, vecs, out, 16, 0);
        } else if (n_par >= 1024) {
            int ksplit = (n_par >= 4096) ? 2 : 4;
            size_t zs = (size_t)n_par * 256;
            level_mma<<<dim3(n_par / MTILE, 2, ksplit), 256, SMEM_REQ>>>(
                cur, nullptr, part, 16 / ksplit, zs);
            reduce_tanh<<<(unsigned)(zs / 1024), 256>>>(part, vecs, out, ksplit, zs);
        } else {
            level_small<<<n_par * 8, 256>>>(cur, Wl, Wr, vecs, out);
        }
        cur = out;
    }
}